// round 15
// baseline (speedup 1.0000x reference)
#include <cuda_runtime.h>
#include <cuda_fp16.h>
#include <cstdint>

// ---------------------------------------------------------------------------
// GraphSAGE: 3x SAGEConv(mean) + linear head.
// N=100000, E=3200000, dims 64 -> 64 -> 32 -> 16 -> 1
//
// v15 = v14 (fp16 T + HADD2 gathers, f32x2 GEMMs, merged scan) +
//   * hist/fill vectorized to 4 edges/thread (int4 index loads, 4 independent
//     atomic/store chains) — R14 ncu showed fill latency-bound (issue 4.6%,
//     MLP=1/thread).
// ---------------------------------------------------------------------------

#define N_NODES 100000
#define MAX_E   3200000

__device__ __half g_t[(size_t)N_NODES * 64];
__device__ float  g_u[(size_t)N_NODES * 64];
__device__ float  g_h[(size_t)N_NODES * 64];
__device__ float  g_inv[N_NODES];
__device__ int    g_cnt[N_NODES];              // ALWAYS 0 at entry (scan23 resets)
__device__ int    g_rs[N_NODES + 1];
__device__ int    g_cur[N_NODES];
__device__ int    g_csr[MAX_E];
__device__ int    g_bsum[512];

static inline int cdiv(long long a, int b) { return (int)((a + b - 1) / b); }

// ---------------- helpers ----------------
__device__ __forceinline__ unsigned long long dup2(float a) {
    unsigned long long r;
    asm("mov.b64 %0, {%1, %1};" : "=l"(r) : "f"(a));
    return r;
}
__device__ __forceinline__ unsigned long long pack2(float a, float b) {
    unsigned long long r;
    asm("mov.b64 %0, {%1, %2};" : "=l"(r) : "f"(a), "f"(b));
    return r;
}
__device__ __forceinline__ void unpack2(unsigned long long v, float& a, float& b) {
    asm("mov.b64 {%0, %1}, %2;" : "=f"(a), "=f"(b) : "l"(v));
}
__device__ __forceinline__ void fma2(unsigned long long& acc,
                                     unsigned long long x, unsigned long long w) {
    asm("fma.rn.f32x2 %0, %1, %2, %0;" : "+l"(acc) : "l"(x), "l"(w));
}
__device__ __forceinline__ __half2 as_h2(unsigned int u) {
    return *reinterpret_cast<__half2*>(&u);
}
__device__ __forceinline__ void hacc4(__half2* a, const uint4& v) {
    a[0] = __hadd2(a[0], as_h2(v.x));
    a[1] = __hadd2(a[1], as_h2(v.y));
    a[2] = __hadd2(a[2], as_h2(v.z));
    a[3] = __hadd2(a[3], as_h2(v.w));
}

// ---------------- CSR build: 4 edges/thread, int4 loads ----------------
__global__ void hist_kernel(const int* __restrict__ dst, int* __restrict__ cnt, int e) {
    int base = (blockIdx.x * blockDim.x + threadIdx.x) * 4;
    if (base + 4 <= e) {
        int4 d = *reinterpret_cast<const int4*>(dst + base);
        atomicAdd(&cnt[d.x], 1);
        atomicAdd(&cnt[d.y], 1);
        atomicAdd(&cnt[d.z], 1);
        atomicAdd(&cnt[d.w], 1);
    } else {
        for (int i = base; i < e; i++) atomicAdd(&cnt[dst[i]], 1);
    }
}

__global__ void __launch_bounds__(256)
scan1_kernel(const int* __restrict__ cnt, int* __restrict__ rs,
             int* __restrict__ bsum, int n) {
    __shared__ int sm[256];
    int tid = threadIdx.x;
    int gi = blockIdx.x * 256 + tid;
    int v = (gi < n) ? cnt[gi] : 0;
    sm[tid] = v;
    __syncthreads();
#pragma unroll
    for (int off = 1; off < 256; off <<= 1) {
        int t = (tid >= off) ? sm[tid - off] : 0;
        __syncthreads();
        sm[tid] += t;
        __syncthreads();
    }
    if (gi < n) rs[gi] = sm[tid] - v;
    if (tid == 255) bsum[blockIdx.x] = sm[255];
}

// merged scan2+scan3: each block reduces bsum[0..b) itself (<=391 ints, L2-hot).
__global__ void __launch_bounds__(256)
scan23_kernel(int* __restrict__ cnt, int* __restrict__ rs, int* __restrict__ cur,
              float* __restrict__ inv, const int* __restrict__ bsum, int n) {
    __shared__ int red[256];
    int tid = threadIdx.x;
    int b = blockIdx.x;

    int local = 0;
    for (int i = tid; i < b; i += 256) local += __ldg(bsum + i);
    red[tid] = local;
    __syncthreads();
#pragma unroll
    for (int off = 128; off > 0; off >>= 1) {
        if (tid < off) red[tid] += red[tid + off];
        __syncthreads();
    }
    int prefix = red[0];

    int gi = b * 256 + tid;
    if (gi >= n) return;
    int rsv = rs[gi] + prefix;
    rs[gi] = rsv;
    cur[gi] = rsv;
    int c = cnt[gi];
    cnt[gi] = 0;
    inv[gi] = 1.0f / fmaxf((float)c, 1.0f);
    if (gi == n - 1) rs[n] = rsv + c;
}

__global__ void fill_kernel(const int* __restrict__ src, const int* __restrict__ dst,
                            int* __restrict__ cur, int* __restrict__ csr, int e) {
    int base = (blockIdx.x * blockDim.x + threadIdx.x) * 4;
    if (base + 4 <= e) {
        int4 s = *reinterpret_cast<const int4*>(src + base);
        int4 d = *reinterpret_cast<const int4*>(dst + base);
        int p0 = atomicAdd(&cur[d.x], 1);
        int p1 = atomicAdd(&cur[d.y], 1);
        int p2 = atomicAdd(&cur[d.z], 1);
        int p3 = atomicAdd(&cur[d.w], 1);
        csr[p0] = s.x;
        csr[p1] = s.y;
        csr[p2] = s.z;
        csr[p3] = s.w;
    } else {
        for (int i = base; i < e; i++) {
            int p = atomicAdd(&cur[dst[i]], 1);
            csr[p] = src[i];
        }
    }
}

// ---------------- tiled dual GEMM: t(h16) = X@Wl, u(f32) = X@Wr + b --------
template <int DIN, int DOUT>
__global__ void __launch_bounds__(256)
gemm_kernel(const float* __restrict__ X,
            const float* __restrict__ Wl, const float* __restrict__ Wr,
            const float* __restrict__ B,
            __half* __restrict__ T, float* __restrict__ U,
            int n, int ntiles) {
    constexpr int P  = DOUT / 2;
    constexpr int G  = 32 / P;
    constexpr int WT = 8 * G;
    constexpr int BT = 8 * WT;
    constexpr int XP = DIN + 4;

    extern __shared__ float sm[];
    float* sW = sm;
    float* sX = sm + DIN * 2 * DOUT;

    for (int i = threadIdx.x; i < DIN * DOUT; i += 256) {
        int k = i / DOUT, j = i % DOUT;
        sW[k * 2 * DOUT + 4 * (j >> 1) + (j & 1)]     = Wl[i];
        sW[k * 2 * DOUT + 4 * (j >> 1) + 2 + (j & 1)] = Wr[i];
    }

    int lane = threadIdx.x & 31;
    int warp = threadIdx.x >> 5;
    int g = lane / P;
    int p = lane % P;

    float2 bb = *reinterpret_cast<const float2*>(B + 2 * p);

    for (int tile = blockIdx.x; tile < ntiles; tile += gridDim.x) {
        int nbase = tile * BT;
        __syncthreads();
        for (int i = threadIdx.x; i < BT * (DIN / 4); i += 256) {
            int node = i / (DIN / 4), kq = i % (DIN / 4);
            int gn = nbase + node;
            float4 v = make_float4(0.f, 0.f, 0.f, 0.f);
            if (gn < n) v = *reinterpret_cast<const float4*>(X + (size_t)gn * DIN + 4 * kq);
            *reinterpret_cast<float4*>(&sX[node * XP + 4 * kq]) = v;
        }
        __syncthreads();

        int ln = warp * WT + g * 8;

        unsigned long long aL0[4], aL1[4], aR0[4], aR1[4];
#pragma unroll
        for (int m = 0; m < 4; m++) {
            aL0[m] = 0ull; aL1[m] = 0ull;
            aR0[m] = dup2(bb.x); aR1[m] = dup2(bb.y);
        }

#pragma unroll 8
        for (int k = 0; k < DIN; k++) {
            float4 w = *reinterpret_cast<const float4*>(&sW[k * 2 * DOUT + 4 * p]);
            unsigned long long wl0 = dup2(w.x), wl1 = dup2(w.y);
            unsigned long long wr0 = dup2(w.z), wr1 = dup2(w.w);
            float xs[8];
#pragma unroll
            for (int m = 0; m < 8; m++) xs[m] = sX[(ln + m) * XP + k];
#pragma unroll
            for (int m = 0; m < 4; m++) {
                unsigned long long xp2 = pack2(xs[2 * m], xs[2 * m + 1]);
                fma2(aL0[m], xp2, wl0);
                fma2(aL1[m], xp2, wl1);
                fma2(aR0[m], xp2, wr0);
                fma2(aR1[m], xp2, wr1);
            }
        }

#pragma unroll
        for (int m = 0; m < 4; m++) {
            float l0a, l0b, l1a, l1b, r0a, r0b, r1a, r1b;
            unpack2(aL0[m], l0a, l0b);
            unpack2(aL1[m], l1a, l1b);
            unpack2(aR0[m], r0a, r0b);
            unpack2(aR1[m], r1a, r1b);
            int gn0 = nbase + ln + 2 * m;
            if (gn0 < n) {
                reinterpret_cast<__half2*>(T)[(size_t)gn0 * P + p] =
                    __floats2half2_rn(l0a, l1a);
                *reinterpret_cast<float2*>(&U[(size_t)gn0 * DOUT + 2 * p]) =
                    make_float2(r0a, r1a);
            }
            if (gn0 + 1 < n) {
                reinterpret_cast<__half2*>(T)[(size_t)(gn0 + 1) * P + p] =
                    __floats2half2_rn(l0b, l1b);
                *reinterpret_cast<float2*>(&U[(size_t)(gn0 + 1) * DOUT + 2 * p]) =
                    make_float2(r0b, r1b);
            }
        }
    }
}

// ---------------- gathers: fp16 rows, HADD2, 4 index chains ----------------

// DOUT=64: row = 128B = 8 lanes x uint4; 4 edges/LDG; 4 chains = 16 edges/iter.
__global__ void __launch_bounds__(256)
gather64_kernel(const int* __restrict__ rs, const int* __restrict__ csr,
                const __half* __restrict__ T, const float* __restrict__ U,
                const float* __restrict__ inv, float* __restrict__ H, int n) {
    int node = (blockIdx.x * blockDim.x + threadIdx.x) >> 5;
    if (node >= n) return;
    int lane = threadIdx.x & 31;
    unsigned q = lane >> 3, l8 = lane & 7;

    int beg = rs[node], end = rs[node + 1];
    float iv = inv[node];
    const uint4* Tp = reinterpret_cast<const uint4*>(T);   // 8 uint4 per row

    __half2 hA[4], hB[4];
#pragma unroll
    for (int j = 0; j < 4; j++) { hA[j] = __half2(); hB[j] = __half2(); }

    int i = beg;
    int s0, s1, s2, s3;
    bool have = (i + 16 <= end);
    if (have) {
        s0 = __ldg(csr + i + q);
        s1 = __ldg(csr + i + 4 + q);
        s2 = __ldg(csr + i + 8 + q);
        s3 = __ldg(csr + i + 12 + q);
    }
    while (have) {
        uint4 v0 = __ldg(Tp + (unsigned)s0 * 8u + l8);
        uint4 v1 = __ldg(Tp + (unsigned)s1 * 8u + l8);
        uint4 v2 = __ldg(Tp + (unsigned)s2 * 8u + l8);
        uint4 v3 = __ldg(Tp + (unsigned)s3 * 8u + l8);
        i += 16;
        have = (i + 16 <= end);
        if (have) {
            s0 = __ldg(csr + i + q);
            s1 = __ldg(csr + i + 4 + q);
            s2 = __ldg(csr + i + 8 + q);
            s3 = __ldg(csr + i + 12 + q);
        }
        hacc4(hA, v0); hacc4(hB, v1); hacc4(hA, v2); hacc4(hB, v3);
    }
    {
        int e0 = i + q, e1 = i + 4 + q, e2 = i + 8 + q, e3 = i + 12 + q;
        if (e0 < end) { unsigned s = __ldg(csr + e0); hacc4(hA, __ldg(Tp + s * 8u + l8)); }
        if (e1 < end) { unsigned s = __ldg(csr + e1); hacc4(hB, __ldg(Tp + s * 8u + l8)); }
        if (e2 < end) { unsigned s = __ldg(csr + e2); hacc4(hA, __ldg(Tp + s * 8u + l8)); }
        if (e3 < end) { unsigned s = __ldg(csr + e3); hacc4(hB, __ldg(Tp + s * 8u + l8)); }
    }

    float2 f[4];
#pragma unroll
    for (int j = 0; j < 4; j++) {
        float2 a = __half22float2(hA[j]);
        float2 b = __half22float2(hB[j]);
        f[j].x = a.x + b.x;
        f[j].y = a.y + b.y;
    }
#pragma unroll
    for (int off = 8; off <= 16; off <<= 1) {
#pragma unroll
        for (int j = 0; j < 4; j++) {
            f[j].x += __shfl_down_sync(0xffffffffu, f[j].x, off);
            f[j].y += __shfl_down_sync(0xffffffffu, f[j].y, off);
        }
    }

    if (q == 0) {
        const float4* U4 = reinterpret_cast<const float4*>(U) + (size_t)node * 16 + l8 * 2;
        float4* H4 = reinterpret_cast<float4*>(H) + (size_t)node * 16 + l8 * 2;
        float4 u0 = __ldg(U4), u1 = __ldg(U4 + 1);
        float4 h0, h1;
        h0.x = fmaxf(fmaf(f[0].x, iv, u0.x), 0.0f);
        h0.y = fmaxf(fmaf(f[0].y, iv, u0.y), 0.0f);
        h0.z = fmaxf(fmaf(f[1].x, iv, u0.z), 0.0f);
        h0.w = fmaxf(fmaf(f[1].y, iv, u0.w), 0.0f);
        h1.x = fmaxf(fmaf(f[2].x, iv, u1.x), 0.0f);
        h1.y = fmaxf(fmaf(f[2].y, iv, u1.y), 0.0f);
        h1.z = fmaxf(fmaf(f[3].x, iv, u1.z), 0.0f);
        h1.w = fmaxf(fmaf(f[3].y, iv, u1.w), 0.0f);
        H4[0] = h0; H4[1] = h1;
    }
}

// DOUT=32: row = 64B = 4 lanes x uint4; 8 edges/LDG; 4 chains = 32 edges/iter.
__global__ void __launch_bounds__(256)
gather32_kernel(const int* __restrict__ rs, const int* __restrict__ csr,
                const __half* __restrict__ T, const float* __restrict__ U,
                const float* __restrict__ inv, float* __restrict__ H, int n) {
    int node = (blockIdx.x * blockDim.x + threadIdx.x) >> 5;
    if (node >= n) return;
    int lane = threadIdx.x & 31;
    unsigned g = lane >> 2, l4 = lane & 3;

    int beg = rs[node], end = rs[node + 1];
    float iv = inv[node];
    const uint4* Tp = reinterpret_cast<const uint4*>(T);   // 4 uint4 per row

    __half2 hA[4], hB[4];
#pragma unroll
    for (int j = 0; j < 4; j++) { hA[j] = __half2(); hB[j] = __half2(); }

    int i = beg;
    int s0, s1, s2, s3;
    bool have = (i + 32 <= end);
    if (have) {
        s0 = __ldg(csr + i + g);
        s1 = __ldg(csr + i + 8 + g);
        s2 = __ldg(csr + i + 16 + g);
        s3 = __ldg(csr + i + 24 + g);
    }
    while (have) {
        uint4 v0 = __ldg(Tp + (unsigned)s0 * 4u + l4);
        uint4 v1 = __ldg(Tp + (unsigned)s1 * 4u + l4);
        uint4 v2 = __ldg(Tp + (unsigned)s2 * 4u + l4);
        uint4 v3 = __ldg(Tp + (unsigned)s3 * 4u + l4);
        i += 32;
        have = (i + 32 <= end);
        if (have) {
            s0 = __ldg(csr + i + g);
            s1 = __ldg(csr + i + 8 + g);
            s2 = __ldg(csr + i + 16 + g);
            s3 = __ldg(csr + i + 24 + g);
        }
        hacc4(hA, v0); hacc4(hB, v1); hacc4(hA, v2); hacc4(hB, v3);
    }
    {
        int e0 = i + g, e1 = i + 8 + g, e2 = i + 16 + g, e3 = i + 24 + g;
        if (e0 < end) { unsigned s = __ldg(csr + e0); hacc4(hA, __ldg(Tp + s * 4u + l4)); }
        if (e1 < end) { unsigned s = __ldg(csr + e1); hacc4(hB, __ldg(Tp + s * 4u + l4)); }
        if (e2 < end) { unsigned s = __ldg(csr + e2); hacc4(hA, __ldg(Tp + s * 4u + l4)); }
        if (e3 < end) { unsigned s = __ldg(csr + e3); hacc4(hB, __ldg(Tp + s * 4u + l4)); }
    }

    float2 f[4];
#pragma unroll
    for (int j = 0; j < 4; j++) {
        float2 a = __half22float2(hA[j]);
        float2 b = __half22float2(hB[j]);
        f[j].x = a.x + b.x;
        f[j].y = a.y + b.y;
    }
#pragma unroll
    for (int off = 4; off <= 16; off <<= 1) {
#pragma unroll
        for (int j = 0; j < 4; j++) {
            f[j].x += __shfl_down_sync(0xffffffffu, f[j].x, off);
            f[j].y += __shfl_down_sync(0xffffffffu, f[j].y, off);
        }
    }

    if (g == 0) {
        const float4* U4 = reinterpret_cast<const float4*>(U) + (size_t)node * 8 + l4 * 2;
        float4* H4 = reinterpret_cast<float4*>(H) + (size_t)node * 8 + l4 * 2;
        float4 u0 = __ldg(U4), u1 = __ldg(U4 + 1);
        float4 h0, h1;
        h0.x = fmaxf(fmaf(f[0].x, iv, u0.x), 0.0f);
        h0.y = fmaxf(fmaf(f[0].y, iv, u0.y), 0.0f);
        h0.z = fmaxf(fmaf(f[1].x, iv, u0.z), 0.0f);
        h0.w = fmaxf(fmaf(f[1].y, iv, u0.w), 0.0f);
        h1.x = fmaxf(fmaf(f[2].x, iv, u1.x), 0.0f);
        h1.y = fmaxf(fmaf(f[2].y, iv, u1.y), 0.0f);
        h1.z = fmaxf(fmaf(f[3].x, iv, u1.z), 0.0f);
        h1.w = fmaxf(fmaf(f[3].y, iv, u1.w), 0.0f);
        H4[0] = h0; H4[1] = h1;
    }
}

// DOUT=16 + fused head: row = 32B = 2 lanes x uint4; 16 edges/LDG;
// 4 chains = 64 edges/iter (most nodes tail-only, fully parallel).
__global__ void __launch_bounds__(256)
gather16_head_kernel(const int* __restrict__ rs, const int* __restrict__ csr,
                     const __half* __restrict__ T, const float* __restrict__ U,
                     const float* __restrict__ inv,
                     const float* __restrict__ Wc, const float* __restrict__ bc,
                     float* __restrict__ out, int n) {
    int node = (blockIdx.x * blockDim.x + threadIdx.x) >> 5;
    if (node >= n) return;
    int lane = threadIdx.x & 31;
    unsigned g = lane >> 1, l2 = lane & 1;

    int beg = rs[node], end = rs[node + 1];
    float iv = inv[node];
    const uint4* Tp = reinterpret_cast<const uint4*>(T);   // 2 uint4 per row

    __half2 hA[4], hB[4];
#pragma unroll
    for (int j = 0; j < 4; j++) { hA[j] = __half2(); hB[j] = __half2(); }

    int i = beg;
    int s0, s1, s2, s3;
    bool have = (i + 64 <= end);
    if (have) {
        s0 = __ldg(csr + i + g);
        s1 = __ldg(csr + i + 16 + g);
        s2 = __ldg(csr + i + 32 + g);
        s3 = __ldg(csr + i + 48 + g);
    }
    while (have) {
        uint4 v0 = __ldg(Tp + (unsigned)s0 * 2u + l2);
        uint4 v1 = __ldg(Tp + (unsigned)s1 * 2u + l2);
        uint4 v2 = __ldg(Tp + (unsigned)s2 * 2u + l2);
        uint4 v3 = __ldg(Tp + (unsigned)s3 * 2u + l2);
        i += 64;
        have = (i + 64 <= end);
        if (have) {
            s0 = __ldg(csr + i + g);
            s1 = __ldg(csr + i + 16 + g);
            s2 = __ldg(csr + i + 32 + g);
            s3 = __ldg(csr + i + 48 + g);
        }
        hacc4(hA, v0); hacc4(hB, v1); hacc4(hA, v2); hacc4(hB, v3);
    }
    {
        int e0 = i + g, e1 = i + 16 + g, e2 = i + 32 + g, e3 = i + 48 + g;
        if (e0 < end) { unsigned s = __ldg(csr + e0); hacc4(hA, __ldg(Tp + s * 2u + l2)); }
        if (e1 < end) { unsigned s = __ldg(csr + e1); hacc4(hB, __ldg(Tp + s * 2u + l2)); }
        if (e2 < end) { unsigned s = __ldg(csr + e2); hacc4(hA, __ldg(Tp + s * 2u + l2)); }
        if (e3 < end) { unsigned s = __ldg(csr + e3); hacc4(hB, __ldg(Tp + s * 2u + l2)); }
    }

    float2 f[4];
#pragma unroll
    for (int j = 0; j < 4; j++) {
        float2 a = __half22float2(hA[j]);
        float2 b = __half22float2(hB[j]);
        f[j].x = a.x + b.x;
        f[j].y = a.y + b.y;
    }
#pragma unroll
    for (int off = 2; off <= 16; off <<= 1) {
#pragma unroll
        for (int j = 0; j < 4; j++) {
            f[j].x += __shfl_down_sync(0xffffffffu, f[j].x, off);
            f[j].y += __shfl_down_sync(0xffffffffu, f[j].y, off);
        }
    }

    float partial = 0.0f;
    if (lane < 2) {
        const float4* U4 = reinterpret_cast<const float4*>(U) + (size_t)node * 4 + l2 * 2;
        float4 u0 = __ldg(U4), u1 = __ldg(U4 + 1);
        const float4* W4 = reinterpret_cast<const float4*>(Wc) + l2 * 2;
        float4 w0 = __ldg(W4), w1 = __ldg(W4 + 1);
        float h0 = fmaxf(fmaf(f[0].x, iv, u0.x), 0.0f);
        float h1 = fmaxf(fmaf(f[0].y, iv, u0.y), 0.0f);
        float h2 = fmaxf(fmaf(f[1].x, iv, u0.z), 0.0f);
        float h3 = fmaxf(fmaf(f[1].y, iv, u0.w), 0.0f);
        float h4 = fmaxf(fmaf(f[2].x, iv, u1.x), 0.0f);
        float h5 = fmaxf(fmaf(f[2].y, iv, u1.y), 0.0f);
        float h6 = fmaxf(fmaf(f[3].x, iv, u1.z), 0.0f);
        float h7 = fmaxf(fmaf(f[3].y, iv, u1.w), 0.0f);
        partial = h0 * w0.x + h1 * w0.y + h2 * w0.z + h3 * w0.w
                + h4 * w1.x + h5 * w1.y + h6 * w1.z + h7 * w1.w;
    }
    partial += __shfl_down_sync(0xffffffffu, partial, 1);
    if (lane == 0) out[node] = partial + __ldg(bc);
}

// ---------------------------------------------------------------------------

template <int DIN, int DOUT>
static void launch_gemm(const float* X, const float* Wl, const float* Wr,
                        const float* B, __half* T, float* U, int n) {
    constexpr int BT = 8 * 8 * (32 / (DOUT / 2));
    constexpr int SMEM = (DIN * 2 * DOUT + BT * (DIN + 4)) * (int)sizeof(float);
    int ntiles = cdiv(n, BT);
    cudaFuncSetAttribute(gemm_kernel<DIN, DOUT>,
                         cudaFuncAttributeMaxDynamicSharedMemorySize, SMEM);
    int grid = ntiles < 592 ? ntiles : 592;
    gemm_kernel<DIN, DOUT><<<grid, 256, SMEM>>>(X, Wl, Wr, B, T, U, n, ntiles);
}

extern "C" void kernel_launch(void* const* d_in, const int* in_sizes, int n_in,
                              void* d_out, int out_size) {
    const float* x   = (const float*)d_in[0];
    const int* eidx  = (const int*)d_in[1];
    const float* Wl0 = (const float*)d_in[2];
    const float* Wr0 = (const float*)d_in[3];
    const float* b0  = (const float*)d_in[4];
    const float* Wl1 = (const float*)d_in[5];
    const float* Wr1 = (const float*)d_in[6];
    const float* b1  = (const float*)d_in[7];
    const float* Wl2 = (const float*)d_in[8];
    const float* Wr2 = (const float*)d_in[9];
    const float* b2  = (const float*)d_in[10];
    const float* Wc  = (const float*)d_in[11];
    const float* bc  = (const float*)d_in[12];
    float* out = (float*)d_out;

    const int n = in_sizes[0] / 64;        // 100000
    const int e = in_sizes[1] / 2;         // 3200000
    const int* src = eidx;
    const int* dst = eidx + e;

    __half* t;
    float *u, *h, *inv;
    int *cnt, *rs, *cur, *csr, *bsum;
    cudaGetSymbolAddress((void**)&t, g_t);
    cudaGetSymbolAddress((void**)&u, g_u);
    cudaGetSymbolAddress((void**)&h, g_h);
    cudaGetSymbolAddress((void**)&inv, g_inv);
    cudaGetSymbolAddress((void**)&cnt, g_cnt);
    cudaGetSymbolAddress((void**)&rs, g_rs);
    cudaGetSymbolAddress((void**)&cur, g_cur);
    cudaGetSymbolAddress((void**)&csr, g_csr);
    cudaGetSymbolAddress((void**)&bsum, g_bsum);

    const int nb = cdiv(n, 256);
    const int ne4 = cdiv(cdiv(e, 4), 256);   // blocks for 4-edge/thread kernels

    // --- CSR + inv_deg (built once, reused 3x; scan23 resets cnt) ---
    hist_kernel<<<ne4, 256>>>(dst, cnt, e);
    scan1_kernel<<<nb, 256>>>(cnt, rs, bsum, n);
    scan23_kernel<<<nb, 256>>>(cnt, rs, cur, inv, bsum, n);
    fill_kernel<<<ne4, 256>>>(src, dst, cur, csr, e);

    // --- layer 0: 64 -> 64 ---
    launch_gemm<64, 64>(x, Wl0, Wr0, b0, t, u, n);
    gather64_kernel<<<cdiv((long long)n * 32, 256), 256>>>(rs, csr, t, u, inv, h, n);

    // --- layer 1: 64 -> 32 ---
    launch_gemm<64, 32>(h, Wl1, Wr1, b1, t, u, n);
    gather32_kernel<<<cdiv((long long)n * 32, 256), 256>>>(rs, csr, t, u, inv, h, n);

    // --- layer 2: 32 -> 16, fused with 16 -> 1 head ---
    launch_gemm<32, 16>(h, Wl2, Wr2, b2, t, u, n);
    gather16_head_kernel<<<cdiv((long long)n * 32, 256), 256>>>(rs, csr, t, u, inv,
                                                                Wc, bc, out, n);
}

// round 16
// speedup vs baseline: 1.0191x; 1.0191x over previous
#include <cuda_runtime.h>
#include <cuda_fp16.h>
#include <cstdint>

// ---------------------------------------------------------------------------
// GraphSAGE: 3x SAGEConv(mean) + linear head.
// N=100000, E=3200000, dims 64 -> 64 -> 32 -> 16 -> 1
//
// v16 = v15 (fp16 T + HADD2 gathers, f32x2 GEMMs, merged scan, vectorized
//       hist) + RANK TRICK: hist persists each edge's within-destination rank
//       (the atomicAdd return, previously discarded); fill becomes
//       csr[rs[dst]+rank] = src with ZERO atomics (R15 ncu: fill was
//       L2-atomic-throughput-bound, not latency-bound). cur array removed.
// ---------------------------------------------------------------------------

#define N_NODES 100000
#define MAX_E   3200000

__device__ __half g_t[(size_t)N_NODES * 64];
__device__ float  g_u[(size_t)N_NODES * 64];
__device__ float  g_h[(size_t)N_NODES * 64];
__device__ float  g_inv[N_NODES];
__device__ int    g_cnt[N_NODES];              // ALWAYS 0 at entry (scan23 resets)
__device__ int    g_rs[N_NODES + 1];
__device__ int    g_csr[MAX_E];
__device__ int    g_rank[MAX_E];
__device__ int    g_bsum[512];

static inline int cdiv(long long a, int b) { return (int)((a + b - 1) / b); }

// ---------------- helpers ----------------
__device__ __forceinline__ unsigned long long dup2(float a) {
    unsigned long long r;
    asm("mov.b64 %0, {%1, %1};" : "=l"(r) : "f"(a));
    return r;
}
__device__ __forceinline__ unsigned long long pack2(float a, float b) {
    unsigned long long r;
    asm("mov.b64 %0, {%1, %2};" : "=l"(r) : "f"(a), "f"(b));
    return r;
}
__device__ __forceinline__ void unpack2(unsigned long long v, float& a, float& b) {
    asm("mov.b64 {%0, %1}, %2;" : "=f"(a), "=f"(b) : "l"(v));
}
__device__ __forceinline__ void fma2(unsigned long long& acc,
                                     unsigned long long x, unsigned long long w) {
    asm("fma.rn.f32x2 %0, %1, %2, %0;" : "+l"(acc) : "l"(x), "l"(w));
}
__device__ __forceinline__ __half2 as_h2(unsigned int u) {
    return *reinterpret_cast<__half2*>(&u);
}
__device__ __forceinline__ void hacc4(__half2* a, const uint4& v) {
    a[0] = __hadd2(a[0], as_h2(v.x));
    a[1] = __hadd2(a[1], as_h2(v.y));
    a[2] = __hadd2(a[2], as_h2(v.z));
    a[3] = __hadd2(a[3], as_h2(v.w));
}

// ---------------- CSR build ----------------
// hist: count edges per destination AND persist each edge's rank within its
// destination (atomicAdd return value — free).
__global__ void hist_kernel(const int* __restrict__ dst, int* __restrict__ cnt,
                            int* __restrict__ rank, int e) {
    int base = (blockIdx.x * blockDim.x + threadIdx.x) * 4;
    if (base + 4 <= e) {
        int4 d = *reinterpret_cast<const int4*>(dst + base);
        int4 r;
        r.x = atomicAdd(&cnt[d.x], 1);
        r.y = atomicAdd(&cnt[d.y], 1);
        r.z = atomicAdd(&cnt[d.z], 1);
        r.w = atomicAdd(&cnt[d.w], 1);
        *reinterpret_cast<int4*>(rank + base) = r;
    } else {
        for (int i = base; i < e; i++) rank[i] = atomicAdd(&cnt[dst[i]], 1);
    }
}

__global__ void __launch_bounds__(256)
scan1_kernel(const int* __restrict__ cnt, int* __restrict__ rs,
             int* __restrict__ bsum, int n) {
    __shared__ int sm[256];
    int tid = threadIdx.x;
    int gi = blockIdx.x * 256 + tid;
    int v = (gi < n) ? cnt[gi] : 0;
    sm[tid] = v;
    __syncthreads();
#pragma unroll
    for (int off = 1; off < 256; off <<= 1) {
        int t = (tid >= off) ? sm[tid - off] : 0;
        __syncthreads();
        sm[tid] += t;
        __syncthreads();
    }
    if (gi < n) rs[gi] = sm[tid] - v;
    if (tid == 255) bsum[blockIdx.x] = sm[255];
}

// merged scan2+scan3: each block reduces bsum[0..b) itself (<=391 ints, L2-hot).
// Also: inv_deg, cnt reset, rs[n] = E. (No cur — rank trick removed it.)
__global__ void __launch_bounds__(256)
scan23_kernel(int* __restrict__ cnt, int* __restrict__ rs,
              float* __restrict__ inv, const int* __restrict__ bsum, int n) {
    __shared__ int red[256];
    int tid = threadIdx.x;
    int b = blockIdx.x;

    int local = 0;
    for (int i = tid; i < b; i += 256) local += __ldg(bsum + i);
    red[tid] = local;
    __syncthreads();
#pragma unroll
    for (int off = 128; off > 0; off >>= 1) {
        if (tid < off) red[tid] += red[tid + off];
        __syncthreads();
    }
    int prefix = red[0];

    int gi = b * 256 + tid;
    if (gi >= n) return;
    int rsv = rs[gi] + prefix;
    rs[gi] = rsv;
    int c = cnt[gi];
    cnt[gi] = 0;
    inv[gi] = 1.0f / fmaxf((float)c, 1.0f);
    if (gi == n - 1) rs[n] = rsv + c;
}

// fill: NO atomics — csr[rs[dst] + rank] = src. rs is 400KB, L1/L2-resident.
__global__ void fill_kernel(const int* __restrict__ src, const int* __restrict__ dst,
                            const int* __restrict__ rank, const int* __restrict__ rs,
                            int* __restrict__ csr, int e) {
    int base = (blockIdx.x * blockDim.x + threadIdx.x) * 4;
    if (base + 4 <= e) {
        int4 s = *reinterpret_cast<const int4*>(src + base);
        int4 d = *reinterpret_cast<const int4*>(dst + base);
        int4 r = *reinterpret_cast<const int4*>(rank + base);
        int p0 = __ldg(rs + d.x) + r.x;
        int p1 = __ldg(rs + d.y) + r.y;
        int p2 = __ldg(rs + d.z) + r.z;
        int p3 = __ldg(rs + d.w) + r.w;
        csr[p0] = s.x;
        csr[p1] = s.y;
        csr[p2] = s.z;
        csr[p3] = s.w;
    } else {
        for (int i = base; i < e; i++)
            csr[__ldg(rs + dst[i]) + rank[i]] = src[i];
    }
}

// ---------------- tiled dual GEMM: t(h16) = X@Wl, u(f32) = X@Wr + b --------
template <int DIN, int DOUT>
__global__ void __launch_bounds__(256)
gemm_kernel(const float* __restrict__ X,
            const float* __restrict__ Wl, const float* __restrict__ Wr,
            const float* __restrict__ B,
            __half* __restrict__ T, float* __restrict__ U,
            int n, int ntiles) {
    constexpr int P  = DOUT / 2;
    constexpr int G  = 32 / P;
    constexpr int WT = 8 * G;
    constexpr int BT = 8 * WT;
    constexpr int XP = DIN + 4;

    extern __shared__ float sm[];
    float* sW = sm;
    float* sX = sm + DIN * 2 * DOUT;

    for (int i = threadIdx.x; i < DIN * DOUT; i += 256) {
        int k = i / DOUT, j = i % DOUT;
        sW[k * 2 * DOUT + 4 * (j >> 1) + (j & 1)]     = Wl[i];
        sW[k * 2 * DOUT + 4 * (j >> 1) + 2 + (j & 1)] = Wr[i];
    }

    int lane = threadIdx.x & 31;
    int warp = threadIdx.x >> 5;
    int g = lane / P;
    int p = lane % P;

    float2 bb = *reinterpret_cast<const float2*>(B + 2 * p);

    for (int tile = blockIdx.x; tile < ntiles; tile += gridDim.x) {
        int nbase = tile * BT;
        __syncthreads();
        for (int i = threadIdx.x; i < BT * (DIN / 4); i += 256) {
            int node = i / (DIN / 4), kq = i % (DIN / 4);
            int gn = nbase + node;
            float4 v = make_float4(0.f, 0.f, 0.f, 0.f);
            if (gn < n) v = *reinterpret_cast<const float4*>(X + (size_t)gn * DIN + 4 * kq);
            *reinterpret_cast<float4*>(&sX[node * XP + 4 * kq]) = v;
        }
        __syncthreads();

        int ln = warp * WT + g * 8;

        unsigned long long aL0[4], aL1[4], aR0[4], aR1[4];
#pragma unroll
        for (int m = 0; m < 4; m++) {
            aL0[m] = 0ull; aL1[m] = 0ull;
            aR0[m] = dup2(bb.x); aR1[m] = dup2(bb.y);
        }

#pragma unroll 8
        for (int k = 0; k < DIN; k++) {
            float4 w = *reinterpret_cast<const float4*>(&sW[k * 2 * DOUT + 4 * p]);
            unsigned long long wl0 = dup2(w.x), wl1 = dup2(w.y);
            unsigned long long wr0 = dup2(w.z), wr1 = dup2(w.w);
            float xs[8];
#pragma unroll
            for (int m = 0; m < 8; m++) xs[m] = sX[(ln + m) * XP + k];
#pragma unroll
            for (int m = 0; m < 4; m++) {
                unsigned long long xp2 = pack2(xs[2 * m], xs[2 * m + 1]);
                fma2(aL0[m], xp2, wl0);
                fma2(aL1[m], xp2, wl1);
                fma2(aR0[m], xp2, wr0);
                fma2(aR1[m], xp2, wr1);
            }
        }

#pragma unroll
        for (int m = 0; m < 4; m++) {
            float l0a, l0b, l1a, l1b, r0a, r0b, r1a, r1b;
            unpack2(aL0[m], l0a, l0b);
            unpack2(aL1[m], l1a, l1b);
            unpack2(aR0[m], r0a, r0b);
            unpack2(aR1[m], r1a, r1b);
            int gn0 = nbase + ln + 2 * m;
            if (gn0 < n) {
                reinterpret_cast<__half2*>(T)[(size_t)gn0 * P + p] =
                    __floats2half2_rn(l0a, l1a);
                *reinterpret_cast<float2*>(&U[(size_t)gn0 * DOUT + 2 * p]) =
                    make_float2(r0a, r1a);
            }
            if (gn0 + 1 < n) {
                reinterpret_cast<__half2*>(T)[(size_t)(gn0 + 1) * P + p] =
                    __floats2half2_rn(l0b, l1b);
                *reinterpret_cast<float2*>(&U[(size_t)(gn0 + 1) * DOUT + 2 * p]) =
                    make_float2(r0b, r1b);
            }
        }
    }
}

// ---------------- gathers: fp16 rows, HADD2, 4 index chains ----------------

// DOUT=64: row = 128B = 8 lanes x uint4; 4 edges/LDG; 4 chains = 16 edges/iter.
__global__ void __launch_bounds__(256)
gather64_kernel(const int* __restrict__ rs, const int* __restrict__ csr,
                const __half* __restrict__ T, const float* __restrict__ U,
                const float* __restrict__ inv, float* __restrict__ H, int n) {
    int node = (blockIdx.x * blockDim.x + threadIdx.x) >> 5;
    if (node >= n) return;
    int lane = threadIdx.x & 31;
    unsigned q = lane >> 3, l8 = lane & 7;

    int beg = rs[node], end = rs[node + 1];
    float iv = inv[node];
    const uint4* Tp = reinterpret_cast<const uint4*>(T);   // 8 uint4 per row

    __half2 hA[4], hB[4];
#pragma unroll
    for (int j = 0; j < 4; j++) { hA[j] = __half2(); hB[j] = __half2(); }

    int i = beg;
    int s0, s1, s2, s3;
    bool have = (i + 16 <= end);
    if (have) {
        s0 = __ldg(csr + i + q);
        s1 = __ldg(csr + i + 4 + q);
        s2 = __ldg(csr + i + 8 + q);
        s3 = __ldg(csr + i + 12 + q);
    }
    while (have) {
        uint4 v0 = __ldg(Tp + (unsigned)s0 * 8u + l8);
        uint4 v1 = __ldg(Tp + (unsigned)s1 * 8u + l8);
        uint4 v2 = __ldg(Tp + (unsigned)s2 * 8u + l8);
        uint4 v3 = __ldg(Tp + (unsigned)s3 * 8u + l8);
        i += 16;
        have = (i + 16 <= end);
        if (have) {
            s0 = __ldg(csr + i + q);
            s1 = __ldg(csr + i + 4 + q);
            s2 = __ldg(csr + i + 8 + q);
            s3 = __ldg(csr + i + 12 + q);
        }
        hacc4(hA, v0); hacc4(hB, v1); hacc4(hA, v2); hacc4(hB, v3);
    }
    {
        int e0 = i + q, e1 = i + 4 + q, e2 = i + 8 + q, e3 = i + 12 + q;
        if (e0 < end) { unsigned s = __ldg(csr + e0); hacc4(hA, __ldg(Tp + s * 8u + l8)); }
        if (e1 < end) { unsigned s = __ldg(csr + e1); hacc4(hB, __ldg(Tp + s * 8u + l8)); }
        if (e2 < end) { unsigned s = __ldg(csr + e2); hacc4(hA, __ldg(Tp + s * 8u + l8)); }
        if (e3 < end) { unsigned s = __ldg(csr + e3); hacc4(hB, __ldg(Tp + s * 8u + l8)); }
    }

    float2 f[4];
#pragma unroll
    for (int j = 0; j < 4; j++) {
        float2 a = __half22float2(hA[j]);
        float2 b = __half22float2(hB[j]);
        f[j].x = a.x + b.x;
        f[j].y = a.y + b.y;
    }
#pragma unroll
    for (int off = 8; off <= 16; off <<= 1) {
#pragma unroll
        for (int j = 0; j < 4; j++) {
            f[j].x += __shfl_down_sync(0xffffffffu, f[j].x, off);
            f[j].y += __shfl_down_sync(0xffffffffu, f[j].y, off);
        }
    }

    if (q == 0) {
        const float4* U4 = reinterpret_cast<const float4*>(U) + (size_t)node * 16 + l8 * 2;
        float4* H4 = reinterpret_cast<float4*>(H) + (size_t)node * 16 + l8 * 2;
        float4 u0 = __ldg(U4), u1 = __ldg(U4 + 1);
        float4 h0, h1;
        h0.x = fmaxf(fmaf(f[0].x, iv, u0.x), 0.0f);
        h0.y = fmaxf(fmaf(f[0].y, iv, u0.y), 0.0f);
        h0.z = fmaxf(fmaf(f[1].x, iv, u0.z), 0.0f);
        h0.w = fmaxf(fmaf(f[1].y, iv, u0.w), 0.0f);
        h1.x = fmaxf(fmaf(f[2].x, iv, u1.x), 0.0f);
        h1.y = fmaxf(fmaf(f[2].y, iv, u1.y), 0.0f);
        h1.z = fmaxf(fmaf(f[3].x, iv, u1.z), 0.0f);
        h1.w = fmaxf(fmaf(f[3].y, iv, u1.w), 0.0f);
        H4[0] = h0; H4[1] = h1;
    }
}

// DOUT=32: row = 64B = 4 lanes x uint4; 8 edges/LDG; 4 chains = 32 edges/iter.
__global__ void __launch_bounds__(256)
gather32_kernel(const int* __restrict__ rs, const int* __restrict__ csr,
                const __half* __restrict__ T, const float* __restrict__ U,
                const float* __restrict__ inv, float* __restrict__ H, int n) {
    int node = (blockIdx.x * blockDim.x + threadIdx.x) >> 5;
    if (node >= n) return;
    int lane = threadIdx.x & 31;
    unsigned g = lane >> 2, l4 = lane & 3;

    int beg = rs[node], end = rs[node + 1];
    float iv = inv[node];
    const uint4* Tp = reinterpret_cast<const uint4*>(T);   // 4 uint4 per row

    __half2 hA[4], hB[4];
#pragma unroll
    for (int j = 0; j < 4; j++) { hA[j] = __half2(); hB[j] = __half2(); }

    int i = beg;
    int s0, s1, s2, s3;
    bool have = (i + 32 <= end);
    if (have) {
        s0 = __ldg(csr + i + g);
        s1 = __ldg(csr + i + 8 + g);
        s2 = __ldg(csr + i + 16 + g);
        s3 = __ldg(csr + i + 24 + g);
    }
    while (have) {
        uint4 v0 = __ldg(Tp + (unsigned)s0 * 4u + l4);
        uint4 v1 = __ldg(Tp + (unsigned)s1 * 4u + l4);
        uint4 v2 = __ldg(Tp + (unsigned)s2 * 4u + l4);
        uint4 v3 = __ldg(Tp + (unsigned)s3 * 4u + l4);
        i += 32;
        have = (i + 32 <= end);
        if (have) {
            s0 = __ldg(csr + i + g);
            s1 = __ldg(csr + i + 8 + g);
            s2 = __ldg(csr + i + 16 + g);
            s3 = __ldg(csr + i + 24 + g);
        }
        hacc4(hA, v0); hacc4(hB, v1); hacc4(hA, v2); hacc4(hB, v3);
    }
    {
        int e0 = i + g, e1 = i + 8 + g, e2 = i + 16 + g, e3 = i + 24 + g;
        if (e0 < end) { unsigned s = __ldg(csr + e0); hacc4(hA, __ldg(Tp + s * 4u + l4)); }
        if (e1 < end) { unsigned s = __ldg(csr + e1); hacc4(hB, __ldg(Tp + s * 4u + l4)); }
        if (e2 < end) { unsigned s = __ldg(csr + e2); hacc4(hA, __ldg(Tp + s * 4u + l4)); }
        if (e3 < end) { unsigned s = __ldg(csr + e3); hacc4(hB, __ldg(Tp + s * 4u + l4)); }
    }

    float2 f[4];
#pragma unroll
    for (int j = 0; j < 4; j++) {
        float2 a = __half22float2(hA[j]);
        float2 b = __half22float2(hB[j]);
        f[j].x = a.x + b.x;
        f[j].y = a.y + b.y;
    }
#pragma unroll
    for (int off = 4; off <= 16; off <<= 1) {
#pragma unroll
        for (int j = 0; j < 4; j++) {
            f[j].x += __shfl_down_sync(0xffffffffu, f[j].x, off);
            f[j].y += __shfl_down_sync(0xffffffffu, f[j].y, off);
        }
    }

    if (g == 0) {
        const float4* U4 = reinterpret_cast<const float4*>(U) + (size_t)node * 8 + l4 * 2;
        float4* H4 = reinterpret_cast<float4*>(H) + (size_t)node * 8 + l4 * 2;
        float4 u0 = __ldg(U4), u1 = __ldg(U4 + 1);
        float4 h0, h1;
        h0.x = fmaxf(fmaf(f[0].x, iv, u0.x), 0.0f);
        h0.y = fmaxf(fmaf(f[0].y, iv, u0.y), 0.0f);
        h0.z = fmaxf(fmaf(f[1].x, iv, u0.z), 0.0f);
        h0.w = fmaxf(fmaf(f[1].y, iv, u0.w), 0.0f);
        h1.x = fmaxf(fmaf(f[2].x, iv, u1.x), 0.0f);
        h1.y = fmaxf(fmaf(f[2].y, iv, u1.y), 0.0f);
        h1.z = fmaxf(fmaf(f[3].x, iv, u1.z), 0.0f);
        h1.w = fmaxf(fmaf(f[3].y, iv, u1.w), 0.0f);
        H4[0] = h0; H4[1] = h1;
    }
}

// DOUT=16 + fused head: row = 32B = 2 lanes x uint4; 16 edges/LDG;
// 4 chains = 64 edges/iter (most nodes tail-only, fully parallel).
__global__ void __launch_bounds__(256)
gather16_head_kernel(const int* __restrict__ rs, const int* __restrict__ csr,
                     const __half* __restrict__ T, const float* __restrict__ U,
                     const float* __restrict__ inv,
                     const float* __restrict__ Wc, const float* __restrict__ bc,
                     float* __restrict__ out, int n) {
    int node = (blockIdx.x * blockDim.x + threadIdx.x) >> 5;
    if (node >= n) return;
    int lane = threadIdx.x & 31;
    unsigned g = lane >> 1, l2 = lane & 1;

    int beg = rs[node], end = rs[node + 1];
    float iv = inv[node];
    const uint4* Tp = reinterpret_cast<const uint4*>(T);   // 2 uint4 per row

    __half2 hA[4], hB[4];
#pragma unroll
    for (int j = 0; j < 4; j++) { hA[j] = __half2(); hB[j] = __half2(); }

    int i = beg;
    int s0, s1, s2, s3;
    bool have = (i + 64 <= end);
    if (have) {
        s0 = __ldg(csr + i + g);
        s1 = __ldg(csr + i + 16 + g);
        s2 = __ldg(csr + i + 32 + g);
        s3 = __ldg(csr + i + 48 + g);
    }
    while (have) {
        uint4 v0 = __ldg(Tp + (unsigned)s0 * 2u + l2);
        uint4 v1 = __ldg(Tp + (unsigned)s1 * 2u + l2);
        uint4 v2 = __ldg(Tp + (unsigned)s2 * 2u + l2);
        uint4 v3 = __ldg(Tp + (unsigned)s3 * 2u + l2);
        i += 64;
        have = (i + 64 <= end);
        if (have) {
            s0 = __ldg(csr + i + g);
            s1 = __ldg(csr + i + 16 + g);
            s2 = __ldg(csr + i + 32 + g);
            s3 = __ldg(csr + i + 48 + g);
        }
        hacc4(hA, v0); hacc4(hB, v1); hacc4(hA, v2); hacc4(hB, v3);
    }
    {
        int e0 = i + g, e1 = i + 16 + g, e2 = i + 32 + g, e3 = i + 48 + g;
        if (e0 < end) { unsigned s = __ldg(csr + e0); hacc4(hA, __ldg(Tp + s * 2u + l2)); }
        if (e1 < end) { unsigned s = __ldg(csr + e1); hacc4(hB, __ldg(Tp + s * 2u + l2)); }
        if (e2 < end) { unsigned s = __ldg(csr + e2); hacc4(hA, __ldg(Tp + s * 2u + l2)); }
        if (e3 < end) { unsigned s = __ldg(csr + e3); hacc4(hB, __ldg(Tp + s * 2u + l2)); }
    }

    float2 f[4];
#pragma unroll
    for (int j = 0; j < 4; j++) {
        float2 a = __half22float2(hA[j]);
        float2 b = __half22float2(hB[j]);
        f[j].x = a.x + b.x;
        f[j].y = a.y + b.y;
    }
#pragma unroll
    for (int off = 2; off <= 16; off <<= 1) {
#pragma unroll
        for (int j = 0; j < 4; j++) {
            f[j].x += __shfl_down_sync(0xffffffffu, f[j].x, off);
            f[j].y += __shfl_down_sync(0xffffffffu, f[j].y, off);
        }
    }

    float partial = 0.0f;
    if (lane < 2) {
        const float4* U4 = reinterpret_cast<const float4*>(U) + (size_t)node * 4 + l2 * 2;
        float4 u0 = __ldg(U4), u1 = __ldg(U4 + 1);
        const float4* W4 = reinterpret_cast<const float4*>(Wc) + l2 * 2;
        float4 w0 = __ldg(W4), w1 = __ldg(W4 + 1);
        float h0 = fmaxf(fmaf(f[0].x, iv, u0.x), 0.0f);
        float h1 = fmaxf(fmaf(f[0].y, iv, u0.y), 0.0f);
        float h2 = fmaxf(fmaf(f[1].x, iv, u0.z), 0.0f);
        float h3 = fmaxf(fmaf(f[1].y, iv, u0.w), 0.0f);
        float h4 = fmaxf(fmaf(f[2].x, iv, u1.x), 0.0f);
        float h5 = fmaxf(fmaf(f[2].y, iv, u1.y), 0.0f);
        float h6 = fmaxf(fmaf(f[3].x, iv, u1.z), 0.0f);
        float h7 = fmaxf(fmaf(f[3].y, iv, u1.w), 0.0f);
        partial = h0 * w0.x + h1 * w0.y + h2 * w0.z + h3 * w0.w
                + h4 * w1.x + h5 * w1.y + h6 * w1.z + h7 * w1.w;
    }
    partial += __shfl_down_sync(0xffffffffu, partial, 1);
    if (lane == 0) out[node] = partial + __ldg(bc);
}

// ---------------------------------------------------------------------------

template <int DIN, int DOUT>
static void launch_gemm(const float* X, const float* Wl, const float* Wr,
                        const float* B, __half* T, float* U, int n) {
    constexpr int BT = 8 * 8 * (32 / (DOUT / 2));
    constexpr int SMEM = (DIN * 2 * DOUT + BT * (DIN + 4)) * (int)sizeof(float);
    int ntiles = cdiv(n, BT);
    cudaFuncSetAttribute(gemm_kernel<DIN, DOUT>,
                         cudaFuncAttributeMaxDynamicSharedMemorySize, SMEM);
    int grid = ntiles < 592 ? ntiles : 592;
    gemm_kernel<DIN, DOUT><<<grid, 256, SMEM>>>(X, Wl, Wr, B, T, U, n, ntiles);
}

extern "C" void kernel_launch(void* const* d_in, const int* in_sizes, int n_in,
                              void* d_out, int out_size) {
    const float* x   = (const float*)d_in[0];
    const int* eidx  = (const int*)d_in[1];
    const float* Wl0 = (const float*)d_in[2];
    const float* Wr0 = (const float*)d_in[3];
    const float* b0  = (const float*)d_in[4];
    const float* Wl1 = (const float*)d_in[5];
    const float* Wr1 = (const float*)d_in[6];
    const float* b1  = (const float*)d_in[7];
    const float* Wl2 = (const float*)d_in[8];
    const float* Wr2 = (const float*)d_in[9];
    const float* b2  = (const float*)d_in[10];
    const float* Wc  = (const float*)d_in[11];
    const float* bc  = (const float*)d_in[12];
    float* out = (float*)d_out;

    const int n = in_sizes[0] / 64;        // 100000
    const int e = in_sizes[1] / 2;         // 3200000
    const int* src = eidx;
    const int* dst = eidx + e;

    __half* t;
    float *u, *h, *inv;
    int *cnt, *rs, *csr, *rank, *bsum;
    cudaGetSymbolAddress((void**)&t, g_t);
    cudaGetSymbolAddress((void**)&u, g_u);
    cudaGetSymbolAddress((void**)&h, g_h);
    cudaGetSymbolAddress((void**)&inv, g_inv);
    cudaGetSymbolAddress((void**)&cnt, g_cnt);
    cudaGetSymbolAddress((void**)&rs, g_rs);
    cudaGetSymbolAddress((void**)&csr, g_csr);
    cudaGetSymbolAddress((void**)&rank, g_rank);
    cudaGetSymbolAddress((void**)&bsum, g_bsum);

    const int nb = cdiv(n, 256);
    const int ne4 = cdiv(cdiv(e, 4), 256);   // blocks for 4-edge/thread kernels

    // --- CSR + inv_deg (built once, reused 3x; scan23 resets cnt) ---
    hist_kernel<<<ne4, 256>>>(dst, cnt, rank, e);
    scan1_kernel<<<nb, 256>>>(cnt, rs, bsum, n);
    scan23_kernel<<<nb, 256>>>(cnt, rs, inv, bsum, n);
    fill_kernel<<<ne4, 256>>>(src, dst, rank, rs, csr, e);

    // --- layer 0: 64 -> 64 ---
    launch_gemm<64, 64>(x, Wl0, Wr0, b0, t, u, n);
    gather64_kernel<<<cdiv((long long)n * 32, 256), 256>>>(rs, csr, t, u, inv, h, n);

    // --- layer 1: 64 -> 32 ---
    launch_gemm<64, 32>(h, Wl1, Wr1, b1, t, u, n);
    gather32_kernel<<<cdiv((long long)n * 32, 256), 256>>>(rs, csr, t, u, inv, h, n);

    // --- layer 2: 32 -> 16, fused with 16 -> 1 head ---
    launch_gemm<32, 16>(h, Wl2, Wr2, b2, t, u, n);
    gather16_head_kernel<<<cdiv((long long)n * 32, 256), 256>>>(rs, csr, t, u, inv,
                                                                Wc, bc, out, n);
}